// round 6
// baseline (speedup 1.0000x reference)
#include <cuda_runtime.h>

// Fused pre-norm attention-downsampling:
//   out[b,s,:] = q[b,s,:] + sum_f (LN(q[b,s]) . LN(k[b,4s+f])) * LN(v[b,4s+f])
// B=4, Sq=2048, Skv=8192, D=1024, factor=4.
// R5: register-diet version of the R2 block-per-row design.
//  - w/b staged in smem; k and v re-read from L1/L2 instead of being held in
//    registers across phases; v stats folded into phase 1.
//  - 18-value phase-1 reduction + 4-value phase-2 (dot) reduction.
//  - __launch_bounds__(256,5): 5 CTAs/SM -> 62.5% occupancy.

#define DD 1024
#define NT 256
#define NW 8
#define FACTOR 4
#define LN_EPS 1e-5f
#define NR1 18
#define SMB (NW * NR1)   // 144 floats of warp partials, bcast after

// Batched block reduction of N values, 2 barriers.
template <int N>
__device__ __forceinline__ void block_reduce(float (&val)[N], float* sm) {
#pragma unroll
    for (int i = 0; i < N; i++) {
#pragma unroll
        for (int o = 16; o; o >>= 1)
            val[i] += __shfl_xor_sync(0xffffffffu, val[i], o);
    }
    const int w = threadIdx.x >> 5;
    const int l = threadIdx.x & 31;
    if (l == 0) {
#pragma unroll
        for (int i = 0; i < N; i++) sm[w * N + i] = val[i];
    }
    __syncthreads();
    if (threadIdx.x < N) {
        float t = 0.f;
#pragma unroll
        for (int j = 0; j < NW; j++) t += sm[j * N + threadIdx.x];
        sm[SMB + threadIdx.x] = t;
    }
    __syncthreads();
#pragma unroll
    for (int i = 0; i < N; i++) val[i] = sm[SMB + i];
}

__device__ __forceinline__ float hsum(const float4 a) {
    return (a.x + a.y) + (a.z + a.w);
}
__device__ __forceinline__ float hsq(const float4 a) {
    return (a.x * a.x + a.y * a.y) + (a.z * a.z + a.w * a.w);
}

__global__ __launch_bounds__(NT, 5) void attn_ds_kernel(
    const float* __restrict__ q, const float* __restrict__ k,
    const float* __restrict__ v, const float* __restrict__ lnw,
    const float* __restrict__ lnb, float* __restrict__ out) {
    __shared__ float sm[SMB + NR1];
    __shared__ float4 sw[DD / 4];
    __shared__ float4 sb[DD / 4];

    const int bid = blockIdx.x;        // b*2048 + s
    const int b = bid >> 11;
    const int s = bid & 2047;
    const int t = threadIdx.x;
    const float invD = 1.0f / (float)DD;

    const float4* qp = (const float4*)q + (size_t)bid * (DD / 4);
    const size_t kvo = ((size_t)b * 8192 + (size_t)s * FACTOR) * (DD / 4);
    const float4* kp = (const float4*)k + kvo;
    const float4* vp = (const float4*)v + kvo;

    // Stage w/b to smem; ordering covered by phase-1 reduction's barrier.
    sw[t] = ((const float4*)lnw)[t];
    sb[t] = ((const float4*)lnb)[t];

    // ---- Phase 1: all first-moment/second-moment stats in ONE reduction ----
    // r1 layout: [0]=Σq [1]=Σq² [2+2f]=Σk_f [3+2f]=Σk_f² [10+2f]=Σv_f [11+2f]=Σv_f²
    float r1[NR1];
    const float4 qv = qp[t];           // kept live: residual accumulator
    r1[0] = hsum(qv);
    r1[1] = hsq(qv);
#pragma unroll
    for (int f = 0; f < FACTOR; f++) {
        const float4 kf = kp[f * (DD / 4) + t];
        r1[2 + 2 * f] = hsum(kf);
        r1[3 + 2 * f] = hsq(kf);
    }
#pragma unroll
    for (int f = 0; f < FACTOR; f++) {
        const float4 vf = vp[f * (DD / 4) + t];
        r1[10 + 2 * f] = hsum(vf);
        r1[11 + 2 * f] = hsq(vf);
    }
    block_reduce<NR1>(r1, sm);

    // LN(q) in registers (4 floats).
    const float muq = r1[0] * invD;
    const float rsq = rsqrtf(fmaf(-muq, muq, r1[1] * invD) + LN_EPS);
    const float4 wq = sw[t];
    const float4 bq = sb[t];
    float4 qn;
    qn.x = fmaf((qv.x - muq) * rsq, wq.x, bq.x);
    qn.y = fmaf((qv.y - muq) * rsq, wq.y, bq.y);
    qn.z = fmaf((qv.z - muq) * rsq, wq.z, bq.z);
    qn.w = fmaf((qv.w - muq) * rsq, wq.w, bq.w);

    // ---- Phase 2: re-read k from cache, reduce the 4 dot products ----
    float dots[FACTOR];
#pragma unroll
    for (int f = 0; f < FACTOR; f++) {
        const float muk = r1[2 + 2 * f] * invD;
        const float rsk =
            rsqrtf(fmaf(-muk, muk, r1[3 + 2 * f] * invD) + LN_EPS);
        const float4 kf = kp[f * (DD / 4) + t];   // L1/L2 hit
        float4 d;
        d.x = qn.x * fmaf((kf.x - muk) * rsk, wq.x, bq.x);
        d.y = qn.y * fmaf((kf.y - muk) * rsk, wq.y, bq.y);
        d.z = qn.z * fmaf((kf.z - muk) * rsk, wq.z, bq.z);
        d.w = qn.w * fmaf((kf.w - muk) * rsk, wq.w, bq.w);
        dots[f] = hsum(d);
    }
    block_reduce<FACTOR>(dots, sm);

    // ---- Epilogue: residual + Σ wt_f * LN(v_f), v re-read from cache ----
    float4 acc = qv;
#pragma unroll
    for (int f = 0; f < FACTOR; f++) {
        const float wt = dots[f];
        const float muv = r1[10 + 2 * f] * invD;
        const float rsv =
            rsqrtf(fmaf(-muv, muv, r1[11 + 2 * f] * invD) + LN_EPS);
        const float4 vf = vp[f * (DD / 4) + t];   // L1/L2 hit
        acc.x = fmaf(wt, fmaf((vf.x - muv) * rsv, wq.x, bq.x), acc.x);
        acc.y = fmaf(wt, fmaf((vf.y - muv) * rsv, wq.y, bq.y), acc.y);
        acc.z = fmaf(wt, fmaf((vf.z - muv) * rsv, wq.z, bq.z), acc.z);
        acc.w = fmaf(wt, fmaf((vf.w - muv) * rsv, wq.w, bq.w), acc.w);
    }

    ((float4*)out + (size_t)bid * (DD / 4))[t] = acc;
}

extern "C" void kernel_launch(void* const* d_in, const int* in_sizes, int n_in,
                              void* d_out, int out_size) {
    const float* q   = (const float*)d_in[0];  // query     [4,2048,1024]
    const float* k   = (const float*)d_in[1];  // key       [4,8192,1024]
    const float* v   = (const float*)d_in[2];  // value     [4,8192,1024]
    const float* lnw = (const float*)d_in[3];  // ln_weight [1024]
    const float* lnb = (const float*)d_in[4];  // ln_bias   [1024]
    float* out = (float*)d_out;                // [4,2048,1024]

    attn_ds_kernel<<<4 * 2048, NT>>>(q, k, v, lnw, lnb, out);
}

// round 7
// speedup vs baseline: 2.2435x; 2.2435x over previous
#include <cuda_runtime.h>
#include <cstdint>

// Fused pre-norm attention-downsampling:
//   out[b,s,:] = q[b,s,:] + sum_f (LN(q[b,s]) . LN(k[b,4s+f])) * LN(v[b,4s+f])
// B=4, Sq=2048, Skv=8192, D=1024, factor=4.
// R6: R2's proven block-per-row math, but each CTA owns TWO rows.
//     Row 0: register-resident (LDG front-batch), identical to R2.
//     Row 1: prefetched into smem via cp.async.bulk + mbarrier DURING row-0
//     compute, then processed from smem. Fills the DRAM idle gaps that held
//     R2 at 70% of HBM.

#define DD 1024
#define NT 256
#define NW 8
#define FACTOR 4
#define LN_EPS 1e-5f
#define SMB 96            // 8 warps * 12 max reduce values
#define ROW_BYTES 4096    // 1024 floats
#define PRE_BYTES (9 * ROW_BYTES)  // q + 4k + 4v = 36864

// ---- batched block reduction of N values (2 barriers) ----
template <int N>
__device__ __forceinline__ void block_reduce(float (&val)[N], float* sm) {
#pragma unroll
    for (int i = 0; i < N; i++) {
#pragma unroll
        for (int o = 16; o; o >>= 1)
            val[i] += __shfl_xor_sync(0xffffffffu, val[i], o);
    }
    const int w = threadIdx.x >> 5;
    const int l = threadIdx.x & 31;
    if (l == 0) {
#pragma unroll
        for (int i = 0; i < N; i++) sm[w * N + i] = val[i];
    }
    __syncthreads();
    if (threadIdx.x < N) {
        float t = 0.f;
#pragma unroll
        for (int j = 0; j < NW; j++) t += sm[j * N + threadIdx.x];
        sm[SMB + threadIdx.x] = t;
    }
    __syncthreads();
#pragma unroll
    for (int i = 0; i < N; i++) val[i] = sm[SMB + i];
}

__device__ __forceinline__ float hsum(const float4 a) {
    return (a.x + a.y) + (a.z + a.w);
}
__device__ __forceinline__ float hsq(const float4 a) {
    return (a.x * a.x + a.y * a.y) + (a.z * a.z + a.w * a.w);
}

// ---- mbarrier / bulk-async helpers ----
__device__ __forceinline__ void mbar_init(uint32_t mbar, uint32_t cnt) {
    asm volatile("mbarrier.init.shared.b64 [%0], %1;" ::"r"(mbar), "r"(cnt)
                 : "memory");
}
__device__ __forceinline__ void mbar_expect_tx(uint32_t mbar, uint32_t bytes) {
    asm volatile("mbarrier.arrive.expect_tx.shared.b64 _, [%0], %1;" ::"r"(mbar),
                 "r"(bytes)
                 : "memory");
}
__device__ __forceinline__ void bulk_g2s(uint32_t dst, const void* src,
                                         uint32_t bytes, uint32_t mbar) {
    asm volatile(
        "cp.async.bulk.shared::cta.global.mbarrier::complete_tx::bytes "
        "[%0], [%1], %2, [%3];" ::"r"(dst),
        "l"(src), "r"(bytes), "r"(mbar)
        : "memory");
}
__device__ __forceinline__ void mbar_wait(uint32_t mbar, uint32_t parity) {
    uint32_t done;
    asm volatile(
        "{\n\t.reg .pred p;\n\t"
        "mbarrier.try_wait.parity.acquire.cta.shared::cta.b64 p, [%1], %2;\n\t"
        "selp.b32 %0, 1, 0, p;\n\t}"
        : "=r"(done)
        : "r"(mbar), "r"(parity)
        : "memory");
    if (!done) {
        asm volatile(
            "{\n\t.reg .pred P1;\n\t"
            "WL_%=:\n\t"
            "mbarrier.try_wait.parity.acquire.cta.shared::cta.b64 P1, [%0], %1;\n\t"
            "@P1 bra.uni WD_%=;\n\t"
            "bra.uni WL_%=;\n\t"
            "WD_%=:\n\t}" ::"r"(mbar),
            "r"(parity)
            : "memory");
    }
}

// ---- R2 row math: qv/kr/vr already loaded, writes out the row ----
__device__ __forceinline__ void row_math(const float4 qv, const float4 (&kr)[4],
                                         const float4 (&vr)[4], const float4 wv,
                                         const float4 bv, float* sm,
                                         float4* outp, int t) {
    const float invD = 1.0f / (float)DD;

    // Phase 1: q + k stats (10 values).
    float r1[10];
    r1[0] = hsum(qv);
    r1[1] = hsq(qv);
#pragma unroll
    for (int f = 0; f < FACTOR; f++) {
        r1[2 + 2 * f] = hsum(kr[f]);
        r1[3 + 2 * f] = hsq(kr[f]);
    }
    block_reduce<10>(r1, sm);

    const float mu = r1[0] * invD;
    const float rs = rsqrtf(fmaf(-mu, mu, r1[1] * invD) + LN_EPS);
    float4 qn;
    qn.x = fmaf((qv.x - mu) * rs, wv.x, bv.x);
    qn.y = fmaf((qv.y - mu) * rs, wv.y, bv.y);
    qn.z = fmaf((qv.z - mu) * rs, wv.z, bv.z);
    qn.w = fmaf((qv.w - mu) * rs, wv.w, bv.w);

    // Phase 2: dot partials + v stats (12 values).
    float r2[12];
#pragma unroll
    for (int f = 0; f < FACTOR; f++) {
        const float muk = r1[2 + 2 * f] * invD;
        const float rsk =
            rsqrtf(fmaf(-muk, muk, r1[3 + 2 * f] * invD) + LN_EPS);
        const float4 kv = kr[f];
        const float knx = fmaf((kv.x - muk) * rsk, wv.x, bv.x);
        const float kny = fmaf((kv.y - muk) * rsk, wv.y, bv.y);
        const float knz = fmaf((kv.z - muk) * rsk, wv.z, bv.z);
        const float knw = fmaf((kv.w - muk) * rsk, wv.w, bv.w);
        r2[f] = (knx * qn.x + kny * qn.y) + (knz * qn.z + knw * qn.w);
        r2[4 + f] = hsum(vr[f]);
        r2[8 + f] = hsq(vr[f]);
    }
    block_reduce<12>(r2, sm);

    // Epilogue: residual + weighted LN(v).
    float4 acc = qv;
#pragma unroll
    for (int f = 0; f < FACTOR; f++) {
        const float wt = r2[f];
        const float muv = r2[4 + f] * invD;
        const float rsv =
            rsqrtf(fmaf(-muv, muv, r2[8 + f] * invD) + LN_EPS);
        const float4 vv = vr[f];
        acc.x = fmaf(wt, fmaf((vv.x - muv) * rsv, wv.x, bv.x), acc.x);
        acc.y = fmaf(wt, fmaf((vv.y - muv) * rsv, wv.y, bv.y), acc.y);
        acc.z = fmaf(wt, fmaf((vv.z - muv) * rsv, wv.z, bv.z), acc.z);
        acc.w = fmaf(wt, fmaf((vv.w - muv) * rsv, wv.w, bv.w), acc.w);
    }
    outp[t] = acc;
}

__global__ __launch_bounds__(NT, 4) void attn_ds_kernel(
    const float* __restrict__ q, const float* __restrict__ k,
    const float* __restrict__ v, const float* __restrict__ lnw,
    const float* __restrict__ lnb, float* __restrict__ out) {
    __shared__ float sm[SMB + 12];
    __shared__ float4 sq[DD / 4];               // row1 q      (4 KB)
    __shared__ float4 sk[FACTOR * (DD / 4)];    // row1 k      (16 KB)
    __shared__ float4 sv[FACTOR * (DD / 4)];    // row1 v      (16 KB)
    __shared__ __align__(8) unsigned long long mbar_s;

    const int t = threadIdx.x;
    const int r0 = blockIdx.x * 2;          // rows r0, r0+1; never cross batch
    const int b = r0 >> 11;
    const int s0 = r0 & 2047;

    const float4* qp0 = (const float4*)q + (size_t)r0 * (DD / 4);
    const size_t kvo0 = ((size_t)b * 8192 + (size_t)s0 * FACTOR) * (DD / 4);
    const float4* kp0 = (const float4*)k + kvo0;
    const float4* vp0 = (const float4*)v + kvo0;

    // ---- row0: front-batched register loads (critical path first) ----
    float4 qv = qp0[t];
    const float4 wv = ((const float4*)lnw)[t];
    const float4 bv = ((const float4*)lnb)[t];
    float4 kr[FACTOR], vr[FACTOR];
#pragma unroll
    for (int f = 0; f < FACTOR; f++) {
        kr[f] = kp0[f * (DD / 4) + t];
        vr[f] = vp0[f * (DD / 4) + t];
    }

    // ---- kick off row1 prefetch (DRAM stays busy through row0 compute) ----
    const uint32_t mbar = (uint32_t)__cvta_generic_to_shared(&mbar_s);
    if (t == 0) {
        mbar_init(mbar, 1);
        mbar_expect_tx(mbar, PRE_BYTES);
        const float4* qp1 = qp0 + (DD / 4);
        const float4* kp1 = kp0 + FACTOR * (DD / 4);
        const float4* vp1 = vp0 + FACTOR * (DD / 4);
        bulk_g2s((uint32_t)__cvta_generic_to_shared(sq), qp1, ROW_BYTES, mbar);
        bulk_g2s((uint32_t)__cvta_generic_to_shared(sk), kp1, 4 * ROW_BYTES, mbar);
        bulk_g2s((uint32_t)__cvta_generic_to_shared(sv), vp1, 4 * ROW_BYTES, mbar);
    }

    // ---- row0 compute + store (identical to R2) ----
    row_math(qv, kr, vr, wv, bv, sm, (float4*)out + (size_t)r0 * (DD / 4), t);

    // ---- row1: wait on prefetch, load from smem, same math ----
    mbar_wait(mbar, 0);
    qv = sq[t];
#pragma unroll
    for (int f = 0; f < FACTOR; f++) {
        kr[f] = sk[f * (DD / 4) + t];
        vr[f] = sv[f * (DD / 4) + t];
    }
    row_math(qv, kr, vr, wv, bv, sm,
             (float4*)out + (size_t)(r0 + 1) * (DD / 4), t);
}

extern "C" void kernel_launch(void* const* d_in, const int* in_sizes, int n_in,
                              void* d_out, int out_size) {
    const float* q   = (const float*)d_in[0];  // query     [4,2048,1024]
    const float* k   = (const float*)d_in[1];  // key       [4,8192,1024]
    const float* v   = (const float*)d_in[2];  // value     [4,8192,1024]
    const float* lnw = (const float*)d_in[3];  // ln_weight [1024]
    const float* lnb = (const float*)d_in[4];  // ln_bias   [1024]
    float* out = (float*)d_out;                // [4,2048,1024]

    attn_ds_kernel<<<4096, NT>>>(q, k, v, lnw, lnb, out);
}